// round 2
// baseline (speedup 1.0000x reference)
#include <cuda_runtime.h>
#include <cuda_bf16.h>
#include <cstdint>

#define N_NODES_MAX 100000
#define NFEAT 128

// Scratch for XF = x @ filters  (allocation-free rule: __device__ global)
__device__ float g_XF[(size_t)N_NODES_MAX * NFEAT];

// ---------------------------------------------------------------------------
// Kernel 0: zero the output (d_out is poisoned to 0xAA before timing)
// ---------------------------------------------------------------------------
__global__ void zero_kernel(float4* __restrict__ out, int n4) {
    int i = blockIdx.x * blockDim.x + threadIdx.x;
    if (i < n4) out[i] = make_float4(0.f, 0.f, 0.f, 0.f);
}

// ---------------------------------------------------------------------------
// Kernel 1: SGEMM  XF[M,128] = x[M,128] @ filters[128,128]
// Classic SMEM-tiled: BM=128, BN=128, BK=8, 256 threads, 8x8 register tile.
// ---------------------------------------------------------------------------
#define GM_BM 128
#define GM_BN 128
#define GM_BK 8
#define GM_TM 8
#define GM_TN 8

__global__ __launch_bounds__(256, 2)
void gemm_kernel(const float* __restrict__ A,   // [M, 128]
                 const float* __restrict__ B,   // [128, 128]
                 int M) {
    __shared__ float As[GM_BK][GM_BM];   // transposed A tile
    __shared__ float Bs[GM_BK][GM_BN];

    const int tid = threadIdx.x;
    const int block_row = blockIdx.x * GM_BM;

    const int tx = tid % 16;             // 16 * TN(8) = 128 cols
    const int ty = tid / 16;             // 16 * TM(8) = 128 rows
    const int row0 = ty * GM_TM;
    const int col0 = tx * GM_TN;

    float acc[GM_TM][GM_TN];
#pragma unroll
    for (int i = 0; i < GM_TM; i++)
#pragma unroll
        for (int j = 0; j < GM_TN; j++) acc[i][j] = 0.f;

    // Per-thread load coords
    const int a_row = tid / 2;           // 0..127
    const int a_col = (tid % 2) * 4;     // 0 or 4
    const int b_row = tid / 32;          // 0..7
    const int b_col = (tid % 32) * 4;    // 0..124

    const int K = NFEAT;
    for (int k0 = 0; k0 < K; k0 += GM_BK) {
        // Load A tile (guard M remainder)
        float4 av;
        const int gr = block_row + a_row;
        if (gr < M)
            av = *(const float4*)(A + (size_t)gr * NFEAT + k0 + a_col);
        else
            av = make_float4(0.f, 0.f, 0.f, 0.f);
        As[a_col + 0][a_row] = av.x;
        As[a_col + 1][a_row] = av.y;
        As[a_col + 2][a_row] = av.z;
        As[a_col + 3][a_row] = av.w;

        // Load B tile
        const float4 bv = *(const float4*)(B + (size_t)(k0 + b_row) * NFEAT + b_col);
        *(float4*)&Bs[b_row][b_col] = bv;

        __syncthreads();

#pragma unroll
        for (int kk = 0; kk < GM_BK; kk++) {
            float a[GM_TM], b[GM_TN];
#pragma unroll
            for (int i = 0; i < GM_TM; i++) a[i] = As[kk][row0 + i];
#pragma unroll
            for (int j = 0; j < GM_TN; j++) b[j] = Bs[kk][col0 + j];
#pragma unroll
            for (int i = 0; i < GM_TM; i++)
#pragma unroll
                for (int j = 0; j < GM_TN; j++)
                    acc[i][j] += a[i] * b[j];
        }
        __syncthreads();
    }

    // Store to scratch
#pragma unroll
    for (int i = 0; i < GM_TM; i++) {
        const int gr = block_row + row0 + i;
        if (gr < M) {
            float4* p = (float4*)(g_XF + (size_t)gr * NFEAT + col0);
            p[0] = make_float4(acc[i][0], acc[i][1], acc[i][2], acc[i][3]);
            p[1] = make_float4(acc[i][4], acc[i][5], acc[i][6], acc[i][7]);
        }
    }
}

// ---------------------------------------------------------------------------
// Kernel 2: edge scatter. edge_dst is SORTED -> register accumulation per
// warp-chunk, flush with atomicAdd only on dst change / chunk end.
// One warp handles EPW consecutive edges; lane l owns float4 feature slice l.
// NOTE: edge indices are int32 (JAX x64 disabled downcasts int64 -> int32).
// ---------------------------------------------------------------------------
#define EPW 64

__global__ __launch_bounds__(256)
void scatter_kernel(const int* __restrict__ esrc,
                    const int* __restrict__ edst,
                    const float* __restrict__ ew,
                    float* __restrict__ out,
                    int E) {
    const int warp = (blockIdx.x * blockDim.x + threadIdx.x) >> 5;
    const int lane = threadIdx.x & 31;

    long long e0 = (long long)warp * EPW;
    if (e0 >= E) return;
    long long e1 = e0 + EPW;
    if (e1 > E) e1 = E;

    const float4* __restrict__ XF4 = (const float4*)g_XF;

    float4 acc = make_float4(0.f, 0.f, 0.f, 0.f);
    int cur = edst[e0];

    for (long long e = e0; e < e1; e++) {
        const int d = edst[e];
        if (d != cur) {
            float* p = out + (size_t)cur * NFEAT + (size_t)lane * 4;
            atomicAdd(p + 0, acc.x);
            atomicAdd(p + 1, acc.y);
            atomicAdd(p + 2, acc.z);
            atomicAdd(p + 3, acc.w);
            acc = make_float4(0.f, 0.f, 0.f, 0.f);
            cur = d;
        }
        const int s = esrc[e];
        const float wt = ew[e];
        const float4 v = XF4[(size_t)s * 32 + lane];   // coalesced 512B row read per warp
        acc.x += wt * v.x;
        acc.y += wt * v.y;
        acc.z += wt * v.z;
        acc.w += wt * v.w;
    }
    // Final flush
    float* p = out + (size_t)cur * NFEAT + (size_t)lane * 4;
    atomicAdd(p + 0, acc.x);
    atomicAdd(p + 1, acc.y);
    atomicAdd(p + 2, acc.z);
    atomicAdd(p + 3, acc.w);
}

// ---------------------------------------------------------------------------
// Launch: zero -> gemm -> scatter (stream-ordered, graph-capturable)
// ---------------------------------------------------------------------------
extern "C" void kernel_launch(void* const* d_in, const int* in_sizes, int n_in,
                              void* d_out, int out_size) {
    const float* x       = (const float*)d_in[0];
    const float* filters = (const float*)d_in[1];
    const int*   esrc    = (const int*)d_in[2];
    const int*   edst    = (const int*)d_in[3];
    const float* ew      = (const float*)d_in[4];
    float*       out     = (float*)d_out;

    const int M = in_sizes[0] / NFEAT;   // 100000
    const int E = in_sizes[4];           // 3200000

    // 1) zero output
    const int n4 = out_size / 4;
    zero_kernel<<<(n4 + 255) / 256, 256>>>((float4*)out, n4);

    // 2) XF = x @ filters
    const int gblocks = (M + GM_BM - 1) / GM_BM;
    gemm_kernel<<<gblocks, 256>>>(x, filters, M);

    // 3) scatter-sum along sorted edge_dst
    const long long nwarps = ((long long)E + EPW - 1) / EPW;
    const long long nthreads = nwarps * 32;
    const int sblocks = (int)((nthreads + 255) / 256);
    scatter_kernel<<<sblocks, 256>>>(esrc, edst, ew, out, E);
}

// round 4
// speedup vs baseline: 1.2014x; 1.2014x over previous
#include <cuda_runtime.h>
#include <cuda_fp16.h>
#include <cstdint>

#define N_NODES_MAX 100000
#define NFEAT 128

// Scratch (allocation-free rule: __device__ globals).
// Referenced ONLY inside kernels — passing a __device__ symbol as a host-side
// kernel argument silently targets the host shadow copy (ATS on GB300!).
__device__ __half g_XFh[(size_t)N_NODES_MAX * NFEAT];   // XF in fp16 (halves gather bytes)
__device__ int    g_rowptr[N_NODES_MAX + 1];            // CSR row pointer from sorted edge_dst

// ---------------------------------------------------------------------------
// Kernel A: build rowptr from sorted edge_dst.
// rowptr[d] = first edge index with edst >= d;  rowptr[N] = E.
// ---------------------------------------------------------------------------
__global__ void rowptr_kernel(const int* __restrict__ edst, int E, int N) {
    int e = blockIdx.x * blockDim.x + threadIdx.x;
    if (e >= E) return;
    int d  = edst[e];
    int dp = (e == 0) ? -1 : edst[e - 1];
    for (int dd = dp + 1; dd <= d; dd++) g_rowptr[dd] = e;
    if (e == E - 1) {
        for (int dd = d + 1; dd <= N; dd++) g_rowptr[dd] = E;
    }
}

// ---------------------------------------------------------------------------
// Kernel B: SGEMM  XF[M,128] = x[M,128] @ filters[128,128], fp32 math,
// fp16 output. BM=128, BK=8, 256 threads, 8x8 register tile.
// ---------------------------------------------------------------------------
#define GM_BM 128
#define GM_BK 8
#define GM_TM 8
#define GM_TN 8

__global__ __launch_bounds__(256, 2)
void gemm_kernel(const float* __restrict__ A,   // [M, 128]
                 const float* __restrict__ B,   // [128, 128]
                 int M) {
    __shared__ float As[GM_BK][GM_BM];   // transposed A tile
    __shared__ float Bs[GM_BK][128];

    const int tid = threadIdx.x;
    const int block_row = blockIdx.x * GM_BM;

    const int tx = tid % 16;
    const int ty = tid / 16;
    const int row0 = ty * GM_TM;
    const int col0 = tx * GM_TN;

    float acc[GM_TM][GM_TN];
#pragma unroll
    for (int i = 0; i < GM_TM; i++)
#pragma unroll
        for (int j = 0; j < GM_TN; j++) acc[i][j] = 0.f;

    const int a_row = tid / 2;
    const int a_col = (tid % 2) * 4;
    const int b_row = tid / 32;
    const int b_col = (tid % 32) * 4;

    for (int k0 = 0; k0 < NFEAT; k0 += GM_BK) {
        float4 av;
        const int gr = block_row + a_row;
        if (gr < M)
            av = *(const float4*)(A + (size_t)gr * NFEAT + k0 + a_col);
        else
            av = make_float4(0.f, 0.f, 0.f, 0.f);
        As[a_col + 0][a_row] = av.x;
        As[a_col + 1][a_row] = av.y;
        As[a_col + 2][a_row] = av.z;
        As[a_col + 3][a_row] = av.w;

        const float4 bv = *(const float4*)(B + (size_t)(k0 + b_row) * NFEAT + b_col);
        *(float4*)&Bs[b_row][b_col] = bv;

        __syncthreads();

#pragma unroll
        for (int kk = 0; kk < GM_BK; kk++) {
            float a[GM_TM], b[GM_TN];
#pragma unroll
            for (int i = 0; i < GM_TM; i++) a[i] = As[kk][row0 + i];
#pragma unroll
            for (int j = 0; j < GM_TN; j++) b[j] = Bs[kk][col0 + j];
#pragma unroll
            for (int i = 0; i < GM_TM; i++)
#pragma unroll
                for (int j = 0; j < GM_TN; j++)
                    acc[i][j] += a[i] * b[j];
        }
        __syncthreads();
    }

    // Store fp16 (8 halves = 16B per row-slice)
#pragma unroll
    for (int i = 0; i < GM_TM; i++) {
        const int gr = block_row + row0 + i;
        if (gr < M) {
            __half2 h[4];
#pragma unroll
            for (int j = 0; j < 4; j++)
                h[j] = __floats2half2_rn(acc[i][2 * j], acc[i][2 * j + 1]);
            *(uint4*)(g_XFh + (size_t)gr * NFEAT + col0) = *(const uint4*)h;
        }
    }
}

// ---------------------------------------------------------------------------
// Kernel C: SpMM — one warp per destination node. Register accumulation,
// single non-atomic store per lane. Degree-0 nodes write zeros, so no
// separate zeroing pass is needed.
// Each lane owns 4 features: reads 8B (4 halves) of the 256B fp16 row.
// ---------------------------------------------------------------------------
__global__ __launch_bounds__(256)
void spmm_kernel(const int* __restrict__ esrc,
                 const float* __restrict__ ew,
                 float* __restrict__ out,
                 int N) {
    const int warp = (blockIdx.x * blockDim.x + threadIdx.x) >> 5;
    const int lane = threadIdx.x & 31;
    if (warp >= N) return;

    const int start = g_rowptr[warp];
    const int end   = g_rowptr[warp + 1];

    const uint2* __restrict__ XF2 = (const uint2*)g_XFh;  // 8B per lane, row stride 32

    float4 acc = make_float4(0.f, 0.f, 0.f, 0.f);
    for (int e = start; e < end; e++) {
        const int   s = __ldg(esrc + e);      // uniform across warp (broadcast)
        const float w = __ldg(ew + e);
        const uint2 hv = XF2[(size_t)s * 32 + lane];
        const __half2 h0 = *reinterpret_cast<const __half2*>(&hv.x);
        const __half2 h1 = *reinterpret_cast<const __half2*>(&hv.y);
        const float2 f0 = __half22float2(h0);
        const float2 f1 = __half22float2(h1);
        acc.x += w * f0.x;
        acc.y += w * f0.y;
        acc.z += w * f1.x;
        acc.w += w * f1.y;
    }
    *(float4*)(out + (size_t)warp * NFEAT + (size_t)lane * 4) = acc;
}

// ---------------------------------------------------------------------------
// Launch: rowptr -> gemm -> spmm (stream-ordered, graph-capturable)
// ---------------------------------------------------------------------------
extern "C" void kernel_launch(void* const* d_in, const int* in_sizes, int n_in,
                              void* d_out, int out_size) {
    const float* x       = (const float*)d_in[0];
    const float* filters = (const float*)d_in[1];
    const int*   esrc    = (const int*)d_in[2];
    const int*   edst    = (const int*)d_in[3];
    const float* ew      = (const float*)d_in[4];
    float*       out     = (float*)d_out;

    const int M = in_sizes[0] / NFEAT;   // 100000 nodes
    const int E = in_sizes[4];           // 3200000 edges

    // 1) CSR rowptr from sorted edge_dst
    rowptr_kernel<<<(E + 255) / 256, 256>>>(edst, E, M);

    // 2) XF = x @ filters   (fp32 math, fp16 store)
    gemm_kernel<<<(M + GM_BM - 1) / GM_BM, 256>>>(x, filters, M);

    // 3) out = A_sparse @ XF  (warp per node, no atomics, writes all rows)
    const long long nthreads = (long long)M * 32;
    spmm_kernel<<<(int)((nthreads + 255) / 256), 256>>>(esrc, ew, out, M);
}

// round 5
// speedup vs baseline: 1.3878x; 1.1552x over previous
#include <cuda_runtime.h>
#include <cuda_fp16.h>
#include <mma.h>
#include <cstdint>

using namespace nvcuda;

#define N_NODES_MAX 100000
#define NFEAT 128

// Scratch (allocation-free rule: __device__ globals, referenced only in kernels)
__device__ __half g_XFh[(size_t)N_NODES_MAX * NFEAT];   // XF in fp16
__device__ __half g_Fh[NFEAT * NFEAT];                  // filters in fp16
__device__ int    g_rowptr[N_NODES_MAX + 1];            // CSR row pointer

// ---------------------------------------------------------------------------
// Kernel A: rowptr from sorted edge_dst (1 load/edge via shuffle).
// ---------------------------------------------------------------------------
__global__ void rowptr_kernel(const int* __restrict__ edst, int E, int N) {
    int e = blockIdx.x * blockDim.x + threadIdx.x;
    if (e >= E) return;
    int d  = edst[e];
    int dp = __shfl_up_sync(0xffffffffu, d, 1);
    if ((threadIdx.x & 31) == 0) dp = (e == 0) ? -1 : edst[e - 1];
    for (int dd = dp + 1; dd <= d; dd++) g_rowptr[dd] = e;
    if (e == E - 1) {
        for (int dd = d + 1; dd <= N; dd++) g_rowptr[dd] = E;
    }
}

// ---------------------------------------------------------------------------
// Kernel B0: filters fp32 -> fp16 (one-time tiny convert, 16384 elems)
// ---------------------------------------------------------------------------
__global__ void fconv_kernel(const float* __restrict__ F) {
    int i = blockIdx.x * blockDim.x + threadIdx.x;
    if (i < NFEAT * NFEAT) g_Fh[i] = __float2half_rn(F[i]);
}

// ---------------------------------------------------------------------------
// Kernel B: tensor-core GEMM  XF[M,128] = x[M,128] @ filters[128,128]
// fp16 HMMA, fp32 accumulate, fp16 output.
// Block = 128 rows x 128 cols, 8 warps; warp w owns a 16x128 stripe.
// x tile converted fp32->fp16 into SMEM; B fragments read from g_Fh (L1).
// ---------------------------------------------------------------------------
#define GB_BM 128

__global__ __launch_bounds__(256)
void gemm_wmma_kernel(const float* __restrict__ A, int M) {
    __shared__ __half As[GB_BM][NFEAT + 8];    // ldm 136 (mult of 8), ~34.8KB
    __shared__ float  stage[8][16 * 16];       // per-warp 16x16 f32 staging, 8KB

    const int tid  = threadIdx.x;
    const int warp = tid >> 5;
    const int lane = tid & 31;
    const int block_row = blockIdx.x * GB_BM;

    // Cooperative load + convert: 128x128 fp32 -> fp16 SMEM
    // 4096 float4 groups, 16 per thread
#pragma unroll
    for (int i = 0; i < 16; i++) {
        const int idx = tid + i * 256;          // 0..4095
        const int row = idx >> 5;               // /32 groups per row
        const int col = (idx & 31) << 2;        // *4
        const int gr  = block_row + row;
        float4 v;
        if (gr < M)
            v = *(const float4*)(A + (size_t)gr * NFEAT + col);
        else
            v = make_float4(0.f, 0.f, 0.f, 0.f);
        __half2 h01 = __floats2half2_rn(v.x, v.y);
        __half2 h23 = __floats2half2_rn(v.z, v.w);
        *(__half2*)&As[row][col + 0] = h01;
        *(__half2*)&As[row][col + 2] = h23;
    }
    __syncthreads();

    // MMA: warp stripe rows [warp*16, warp*16+16), 8 column tiles
    wmma::fragment<wmma::accumulator, 16, 16, 16, float> acc[8];
#pragma unroll
    for (int ct = 0; ct < 8; ct++) wmma::fill_fragment(acc[ct], 0.0f);

#pragma unroll
    for (int kt = 0; kt < 8; kt++) {
        wmma::fragment<wmma::matrix_a, 16, 16, 16, __half, wmma::row_major> a_frag;
        wmma::load_matrix_sync(a_frag, &As[warp * 16][kt * 16], NFEAT + 8);
#pragma unroll
        for (int ct = 0; ct < 8; ct++) {
            wmma::fragment<wmma::matrix_b, 16, 16, 16, __half, wmma::row_major> b_frag;
            wmma::load_matrix_sync(b_frag, g_Fh + (size_t)(kt * 16) * NFEAT + ct * 16, NFEAT);
            wmma::mma_sync(acc[ct], a_frag, b_frag, acc[ct]);
        }
    }

    // Store: per col-tile, stage f32 in SMEM, convert to fp16, write 16B/thread
    const int r  = lane >> 1;            // 0..15
    const int c0 = (lane & 1) * 8;       // 0 or 8
#pragma unroll
    for (int ct = 0; ct < 8; ct++) {
        wmma::store_matrix_sync(&stage[warp][0], acc[ct], 16, wmma::mem_row_major);
        __syncwarp();
        const float* sp = &stage[warp][r * 16 + c0];
        __half2 h[4];
#pragma unroll
        for (int j = 0; j < 4; j++)
            h[j] = __floats2half2_rn(sp[2 * j], sp[2 * j + 1]);
        const int gr = block_row + warp * 16 + r;
        if (gr < M)
            *(uint4*)(g_XFh + (size_t)gr * NFEAT + ct * 16 + c0) = *(const uint4*)h;
        __syncwarp();
    }
}

// ---------------------------------------------------------------------------
// Kernel C: SpMM — one warp per destination node, register accumulation,
// non-atomic stores; degree-0 nodes write zeros (no zero pass needed).
// ---------------------------------------------------------------------------
__global__ __launch_bounds__(256)
void spmm_kernel(const int* __restrict__ esrc,
                 const float* __restrict__ ew,
                 float* __restrict__ out,
                 int N) {
    const int warp = (blockIdx.x * blockDim.x + threadIdx.x) >> 5;
    const int lane = threadIdx.x & 31;
    if (warp >= N) return;

    const int start = g_rowptr[warp];
    const int end   = g_rowptr[warp + 1];

    const uint2* __restrict__ XF2 = (const uint2*)g_XFh;  // 8B per lane

    float4 acc = make_float4(0.f, 0.f, 0.f, 0.f);
    for (int e = start; e < end; e++) {
        const int   s = __ldg(esrc + e);
        const float w = __ldg(ew + e);
        const uint2 hv = XF2[(size_t)s * 32 + lane];
        const float2 f0 = __half22float2(*reinterpret_cast<const __half2*>(&hv.x));
        const float2 f1 = __half22float2(*reinterpret_cast<const __half2*>(&hv.y));
        acc.x += w * f0.x;
        acc.y += w * f0.y;
        acc.z += w * f1.x;
        acc.w += w * f1.y;
    }
    *(float4*)(out + (size_t)warp * NFEAT + (size_t)lane * 4) = acc;
}

// ---------------------------------------------------------------------------
// Launch: rowptr -> fconv -> gemm -> spmm (graph-capturable)
// ---------------------------------------------------------------------------
extern "C" void kernel_launch(void* const* d_in, const int* in_sizes, int n_in,
                              void* d_out, int out_size) {
    const float* x       = (const float*)d_in[0];
    const float* filters = (const float*)d_in[1];
    const int*   esrc    = (const int*)d_in[2];
    const int*   edst    = (const int*)d_in[3];
    const float* ew      = (const float*)d_in[4];
    float*       out     = (float*)d_out;

    const int M = in_sizes[0] / NFEAT;   // 100000 nodes
    const int E = in_sizes[4];           // 3200000 edges

    rowptr_kernel<<<(E + 255) / 256, 256>>>(edst, E, M);
    fconv_kernel<<<(NFEAT * NFEAT + 255) / 256, 256>>>(filters);
    gemm_wmma_kernel<<<(M + GB_BM - 1) / GB_BM, 256>>>(x, M);

    const long long nthreads = (long long)M * 32;
    spmm_kernel<<<(int)((nthreads + 255) / 256), 256>>>(esrc, ew, out, M);
}

// round 6
// speedup vs baseline: 2.0943x; 1.5090x over previous
#include <cuda_runtime.h>
#include <cuda_fp16.h>
#include <mma.h>
#include <cstdint>

using namespace nvcuda;

#define N_NODES_MAX 100000
#define NFEAT 128

// Scratch (allocation-free rule: __device__ globals, referenced only in kernels)
__device__ __half g_XFh[(size_t)N_NODES_MAX * NFEAT];   // XF in fp16
__device__ __half g_Fh[NFEAT * NFEAT];                  // filters in fp16
__device__ int    g_rowptr[N_NODES_MAX + 1];            // CSR row pointer

// ---------------------------------------------------------------------------
// Kernel A: rowptr from sorted edge_dst (1 load/edge via shuffle).
// ---------------------------------------------------------------------------
__global__ void rowptr_kernel(const int* __restrict__ edst, int E, int N) {
    int e = blockIdx.x * blockDim.x + threadIdx.x;
    if (e >= E) return;
    int d  = edst[e];
    int dp = __shfl_up_sync(0xffffffffu, d, 1);
    if ((threadIdx.x & 31) == 0) dp = (e == 0) ? -1 : edst[e - 1];
    for (int dd = dp + 1; dd <= d; dd++) g_rowptr[dd] = e;
    if (e == E - 1) {
        for (int dd = d + 1; dd <= N; dd++) g_rowptr[dd] = E;
    }
}

// ---------------------------------------------------------------------------
// Kernel B0: filters fp32 -> fp16 (one-time tiny convert)
// ---------------------------------------------------------------------------
__global__ void fconv_kernel(const float* __restrict__ F) {
    int i = blockIdx.x * blockDim.x + threadIdx.x;
    if (i < NFEAT * NFEAT) g_Fh[i] = __float2half_rn(F[i]);
}

// ---------------------------------------------------------------------------
// Kernel B: tensor-core GEMM  XF[M,128] = x[M,128] @ filters[128,128]
// fp16 HMMA, fp32 accumulate, fp16 output.
// Filters staged in SMEM once per block (fixes global b_frag feed).
// ---------------------------------------------------------------------------
#define GB_BM 128
#define LDM 136   // 128 + 8 halves pad

__global__ __launch_bounds__(256)
void gemm_wmma_kernel(const float* __restrict__ A, int M) {
    __shared__ __half Bs[NFEAT][LDM];          // filters tile, 34.8KB
    __shared__ __half As[GB_BM][LDM];          // x tile (fp16), 34.8KB
    __shared__ float  stage[8][16 * 16];       // per-warp staging, 8KB

    const int tid  = threadIdx.x;
    const int warp = tid >> 5;
    const int lane = tid & 31;
    const int block_row = blockIdx.x * GB_BM;

    // Stage filters: 16384 halves = 2048 uint4 groups; 8 per thread (coalesced)
#pragma unroll
    for (int i = 0; i < 8; i++) {
        const int g   = tid + i * 256;          // 0..2047
        const int row = g >> 4;                 // 16 groups per 128-half row
        const int col = (g & 15) << 3;          // *8 halves
        const uint4 v = *(const uint4*)(g_Fh + (size_t)row * NFEAT + col);
        *(uint4*)&Bs[row][col] = v;
    }

    // Load + convert x tile: 128x128 fp32 -> fp16 SMEM (16 float4 per thread)
#pragma unroll
    for (int i = 0; i < 16; i++) {
        const int idx = tid + i * 256;          // 0..4095
        const int row = idx >> 5;
        const int col = (idx & 31) << 2;
        const int gr  = block_row + row;
        float4 v;
        if (gr < M)
            v = *(const float4*)(A + (size_t)gr * NFEAT + col);
        else
            v = make_float4(0.f, 0.f, 0.f, 0.f);
        *(__half2*)&As[row][col + 0] = __floats2half2_rn(v.x, v.y);
        *(__half2*)&As[row][col + 2] = __floats2half2_rn(v.z, v.w);
    }
    __syncthreads();

    // MMA: warp owns 16x128 stripe
    wmma::fragment<wmma::accumulator, 16, 16, 16, float> acc[8];
#pragma unroll
    for (int ct = 0; ct < 8; ct++) wmma::fill_fragment(acc[ct], 0.0f);

#pragma unroll
    for (int kt = 0; kt < 8; kt++) {
        wmma::fragment<wmma::matrix_a, 16, 16, 16, __half, wmma::row_major> a_frag;
        wmma::load_matrix_sync(a_frag, &As[warp * 16][kt * 16], LDM);
#pragma unroll
        for (int ct = 0; ct < 8; ct++) {
            wmma::fragment<wmma::matrix_b, 16, 16, 16, __half, wmma::row_major> b_frag;
            wmma::load_matrix_sync(b_frag, &Bs[kt * 16][ct * 16], LDM);
            wmma::mma_sync(acc[ct], a_frag, b_frag, acc[ct]);
        }
    }

    // Store: stage f32 per col-tile, convert to fp16, 16B/thread writes
    const int r  = lane >> 1;
    const int c0 = (lane & 1) * 8;
#pragma unroll
    for (int ct = 0; ct < 8; ct++) {
        wmma::store_matrix_sync(&stage[warp][0], acc[ct], 16, wmma::mem_row_major);
        __syncwarp();
        const float* sp = &stage[warp][r * 16 + c0];
        __half2 h[4];
#pragma unroll
        for (int j = 0; j < 4; j++)
            h[j] = __floats2half2_rn(sp[2 * j], sp[2 * j + 1]);
        const int gr = block_row + warp * 16 + r;
        if (gr < M)
            *(uint4*)(g_XFh + (size_t)gr * NFEAT + ct * 16 + c0) = *(const uint4*)h;
        __syncwarp();
    }
}

// ---------------------------------------------------------------------------
// Kernel C: SpMM — one warp per destination node, unrolled x4 for MLP.
// Register accumulation, non-atomic stores; degree-0 rows write zeros.
// ---------------------------------------------------------------------------
__device__ __forceinline__ void edge_acc(float4& acc, const __half* __restrict__ XFh,
                                         int s, float w, int lane) {
    const uint2 hv = *(const uint2*)(XFh + (size_t)s * NFEAT + lane * 4);
    const float2 f0 = __half22float2(*reinterpret_cast<const __half2*>(&hv.x));
    const float2 f1 = __half22float2(*reinterpret_cast<const __half2*>(&hv.y));
    acc.x += w * f0.x;
    acc.y += w * f0.y;
    acc.z += w * f1.x;
    acc.w += w * f1.y;
}

__global__ __launch_bounds__(256)
void spmm_kernel(const int* __restrict__ esrc,
                 const float* __restrict__ ew,
                 float* __restrict__ out,
                 int N) {
    const int warp = (blockIdx.x * blockDim.x + threadIdx.x) >> 5;
    const int lane = threadIdx.x & 31;
    if (warp >= N) return;

    const int start = g_rowptr[warp];
    const int end   = g_rowptr[warp + 1];

    float4 acc = make_float4(0.f, 0.f, 0.f, 0.f);

    int e = start;
    for (; e + 4 <= end; e += 4) {
        const int   s0 = __ldg(esrc + e + 0);
        const int   s1 = __ldg(esrc + e + 1);
        const int   s2 = __ldg(esrc + e + 2);
        const int   s3 = __ldg(esrc + e + 3);
        const float w0 = __ldg(ew + e + 0);
        const float w1 = __ldg(ew + e + 1);
        const float w2 = __ldg(ew + e + 2);
        const float w3 = __ldg(ew + e + 3);
        edge_acc(acc, g_XFh, s0, w0, lane);
        edge_acc(acc, g_XFh, s1, w1, lane);
        edge_acc(acc, g_XFh, s2, w2, lane);
        edge_acc(acc, g_XFh, s3, w3, lane);
    }
    for (; e < end; e++)
        edge_acc(acc, g_XFh, __ldg(esrc + e), __ldg(ew + e), lane);

    *(float4*)(out + (size_t)warp * NFEAT + (size_t)lane * 4) = acc;
}

// ---------------------------------------------------------------------------
// Launch: rowptr -> fconv -> gemm -> spmm (graph-capturable)
// ---------------------------------------------------------------------------
extern "C" void kernel_launch(void* const* d_in, const int* in_sizes, int n_in,
                              void* d_out, int out_size) {
    const float* x       = (const float*)d_in[0];
    const float* filters = (const float*)d_in[1];
    const int*   esrc    = (const int*)d_in[2];
    const int*   edst    = (const int*)d_in[3];
    const float* ew      = (const float*)d_in[4];
    float*       out     = (float*)d_out;

    const int M = in_sizes[0] / NFEAT;   // 100000 nodes
    const int E = in_sizes[4];           // 3200000 edges

    rowptr_kernel<<<(E + 255) / 256, 256>>>(edst, E, M);
    fconv_kernel<<<(NFEAT * NFEAT + 255) / 256, 256>>>(filters);
    gemm_wmma_kernel<<<(M + GB_BM - 1) / GB_BM, 256>>>(x, M);

    const long long nthreads = (long long)M * 32;
    spmm_kernel<<<(int)((nthreads + 255) / 256), 256>>>(esrc, ew, out, M);
}

// round 7
// speedup vs baseline: 2.3123x; 1.1041x over previous
#include <cuda_runtime.h>
#include <cuda_fp16.h>
#include <mma.h>
#include <cstdint>

using namespace nvcuda;

#define N_NODES_MAX 100000
#define NFEAT 128

// Scratch (allocation-free rule: __device__ globals, referenced only in kernels)
__device__ __half g_XFh[(size_t)N_NODES_MAX * NFEAT];   // XF in fp16
__device__ __half g_Fh[NFEAT * NFEAT];                  // filters in fp16
__device__ int    g_rowptr[N_NODES_MAX + 1];            // CSR row pointer

// ---------------------------------------------------------------------------
// Kernel A: rowptr from sorted edge_dst — 4 edges/thread, one int4 load.
// ---------------------------------------------------------------------------
__global__ void rowptr_kernel(const int* __restrict__ edst, int E, int N) {
    const int t  = blockIdx.x * blockDim.x + threadIdx.x;
    const int e0 = t * 4;
    if (e0 >= E) return;

    int d[4];
    int nvalid;
    if (e0 + 4 <= E) {
        const int4 d4 = __ldg((const int4*)(edst + e0));
        d[0] = d4.x; d[1] = d4.y; d[2] = d4.z; d[3] = d4.w;
        nvalid = 4;
    } else {
        nvalid = E - e0;
        for (int i = 0; i < nvalid; i++) d[i] = __ldg(edst + e0 + i);
    }

    int prev = (e0 == 0) ? -1 : __ldg(edst + e0 - 1);
#pragma unroll
    for (int i = 0; i < 4; i++) {
        if (i < nvalid) {
            for (int dd = prev + 1; dd <= d[i]; dd++) g_rowptr[dd] = e0 + i;
            prev = d[i];
        }
    }
    if (e0 + 4 >= E) {   // thread owning the final edge fills the tail
        for (int dd = prev + 1; dd <= N; dd++) g_rowptr[dd] = E;
    }
}

// ---------------------------------------------------------------------------
// Kernel B0: filters fp32 -> fp16 (one-time tiny convert)
// ---------------------------------------------------------------------------
__global__ void fconv_kernel(const float* __restrict__ F) {
    int i = blockIdx.x * blockDim.x + threadIdx.x;
    if (i < NFEAT * NFEAT) g_Fh[i] = __float2half_rn(F[i]);
}

// ---------------------------------------------------------------------------
// Kernel B: tensor-core GEMM  XF[M,128] = x[M,128] @ filters[128,128]
// fp16 HMMA, fp32 accumulate, fp16 output. Filters staged in SMEM per block.
// ---------------------------------------------------------------------------
#define GB_BM 128
#define LDM 136   // 128 + 8 halves pad

__global__ __launch_bounds__(256)
void gemm_wmma_kernel(const float* __restrict__ A, int M) {
    __shared__ __half Bs[NFEAT][LDM];          // filters tile
    __shared__ __half As[GB_BM][LDM];          // x tile (fp16)
    __shared__ float  stage[8][16 * 16];       // per-warp staging

    const int tid  = threadIdx.x;
    const int warp = tid >> 5;
    const int lane = tid & 31;
    const int block_row = blockIdx.x * GB_BM;

    // Stage filters: 2048 uint4 groups; 8 per thread (coalesced)
#pragma unroll
    for (int i = 0; i < 8; i++) {
        const int g   = tid + i * 256;
        const int row = g >> 4;
        const int col = (g & 15) << 3;
        const uint4 v = *(const uint4*)(g_Fh + (size_t)row * NFEAT + col);
        *(uint4*)&Bs[row][col] = v;
    }

    // Load + convert x tile: 128x128 fp32 -> fp16 SMEM
#pragma unroll
    for (int i = 0; i < 16; i++) {
        const int idx = tid + i * 256;
        const int row = idx >> 5;
        const int col = (idx & 31) << 2;
        const int gr  = block_row + row;
        float4 v;
        if (gr < M)
            v = *(const float4*)(A + (size_t)gr * NFEAT + col);
        else
            v = make_float4(0.f, 0.f, 0.f, 0.f);
        *(__half2*)&As[row][col + 0] = __floats2half2_rn(v.x, v.y);
        *(__half2*)&As[row][col + 2] = __floats2half2_rn(v.z, v.w);
    }
    __syncthreads();

    // MMA: warp owns 16x128 stripe
    wmma::fragment<wmma::accumulator, 16, 16, 16, float> acc[8];
#pragma unroll
    for (int ct = 0; ct < 8; ct++) wmma::fill_fragment(acc[ct], 0.0f);

#pragma unroll
    for (int kt = 0; kt < 8; kt++) {
        wmma::fragment<wmma::matrix_a, 16, 16, 16, __half, wmma::row_major> a_frag;
        wmma::load_matrix_sync(a_frag, &As[warp * 16][kt * 16], LDM);
#pragma unroll
        for (int ct = 0; ct < 8; ct++) {
            wmma::fragment<wmma::matrix_b, 16, 16, 16, __half, wmma::row_major> b_frag;
            wmma::load_matrix_sync(b_frag, &Bs[kt * 16][ct * 16], LDM);
            wmma::mma_sync(acc[ct], a_frag, b_frag, acc[ct]);
        }
    }

    // Store: stage f32 per col-tile, convert to fp16, 16B/thread writes
    const int r  = lane >> 1;
    const int c0 = (lane & 1) * 8;
#pragma unroll
    for (int ct = 0; ct < 8; ct++) {
        wmma::store_matrix_sync(&stage[warp][0], acc[ct], 16, wmma::mem_row_major);
        __syncwarp();
        const float* sp = &stage[warp][r * 16 + c0];
        __half2 h[4];
#pragma unroll
        for (int j = 0; j < 4; j++)
            h[j] = __floats2half2_rn(sp[2 * j], sp[2 * j + 1]);
        const int gr = block_row + warp * 16 + r;
        if (gr < M)
            *(uint4*)(g_XFh + (size_t)gr * NFEAT + ct * 16 + c0) = *(const uint4*)h;
        __syncwarp();
    }
}

// ---------------------------------------------------------------------------
// Kernel C: SpMM — one warp per dst node. Vectorized int4/float4 index loads
// over aligned 4-edge blocks, unrolled 8 for MLP. Non-atomic stores.
// ---------------------------------------------------------------------------
__device__ __forceinline__ void edge_acc(float4& acc, int s, float w, int lane) {
    const uint2 hv = *(const uint2*)(g_XFh + (size_t)s * NFEAT + lane * 4);
    const float2 f0 = __half22float2(*reinterpret_cast<const __half2*>(&hv.x));
    const float2 f1 = __half22float2(*reinterpret_cast<const __half2*>(&hv.y));
    acc.x += w * f0.x;
    acc.y += w * f0.y;
    acc.z += w * f1.x;
    acc.w += w * f1.y;
}

__global__ __launch_bounds__(256)
void spmm_kernel(const int* __restrict__ esrc,
                 const float* __restrict__ ew,
                 float* __restrict__ out,
                 int N) {
    const int warp = (blockIdx.x * blockDim.x + threadIdx.x) >> 5;
    const int lane = threadIdx.x & 31;
    if (warp >= N) return;

    const int start = g_rowptr[warp];
    const int end   = g_rowptr[warp + 1];

    float4 acc = make_float4(0.f, 0.f, 0.f, 0.f);

    int e = start;
    // Head: reach 16B alignment for int4/float4 loads
    while (e < end && (e & 3)) {
        edge_acc(acc, __ldg(esrc + e), __ldg(ew + e), lane);
        e++;
    }
    // Main: 8 edges per iteration, 2 vector loads each for idx/weight
    for (; e + 8 <= end; e += 8) {
        const int4   sa = __ldg((const int4*)(esrc + e));
        const int4   sb = __ldg((const int4*)(esrc + e + 4));
        const float4 wa = __ldg((const float4*)(ew + e));
        const float4 wb = __ldg((const float4*)(ew + e + 4));
        edge_acc(acc, sa.x, wa.x, lane);
        edge_acc(acc, sa.y, wa.y, lane);
        edge_acc(acc, sa.z, wa.z, lane);
        edge_acc(acc, sa.w, wa.w, lane);
        edge_acc(acc, sb.x, wb.x, lane);
        edge_acc(acc, sb.y, wb.y, lane);
        edge_acc(acc, sb.z, wb.z, lane);
        edge_acc(acc, sb.w, wb.w, lane);
    }
    // Mid: one 4-edge block
    for (; e + 4 <= end; e += 4) {
        const int4   sa = __ldg((const int4*)(esrc + e));
        const float4 wa = __ldg((const float4*)(ew + e));
        edge_acc(acc, sa.x, wa.x, lane);
        edge_acc(acc, sa.y, wa.y, lane);
        edge_acc(acc, sa.z, wa.z, lane);
        edge_acc(acc, sa.w, wa.w, lane);
    }
    // Tail
    for (; e < end; e++)
        edge_acc(acc, __ldg(esrc + e), __ldg(ew + e), lane);

    *(float4*)(out + (size_t)warp * NFEAT + (size_t)lane * 4) = acc;
}

// ---------------------------------------------------------------------------
// Launch: rowptr -> fconv -> gemm -> spmm (graph-capturable)
// ---------------------------------------------------------------------------
extern "C" void kernel_launch(void* const* d_in, const int* in_sizes, int n_in,
                              void* d_out, int out_size) {
    const float* x       = (const float*)d_in[0];
    const float* filters = (const float*)d_in[1];
    const int*   esrc    = (const int*)d_in[2];
    const int*   edst    = (const int*)d_in[3];
    const float* ew      = (const float*)d_in[4];
    float*       out     = (float*)d_out;

    const int M = in_sizes[0] / NFEAT;   // 100000 nodes
    const int E = in_sizes[4];           // 3200000 edges

    const int rthreads = (E + 3) / 4;
    rowptr_kernel<<<(rthreads + 255) / 256, 256>>>(edst, E, M);
    fconv_kernel<<<(NFEAT * NFEAT + 255) / 256, 256>>>(filters);
    gemm_wmma_kernel<<<(M + GB_BM - 1) / GB_BM, 256>>>(x, M);

    const long long nthreads = (long long)M * 32;
    spmm_kernel<<<(int)((nthreads + 255) / 256), 256>>>(esrc, ew, out, M);
}